// round 1
// baseline (speedup 1.0000x reference)
#include <cuda_runtime.h>
#include <math.h>
#include <stdint.h>

#define BB 8
#define NN 2048
#define DD 384
#define CP 64     // padded channel count (60 enc + 1 ones + 3 zero pad)
#define NF 10

// ---- scratch (device globals; no allocation allowed) ----
__device__ float g_pe[BB * CP * NN];   // pe' : (b, 64, N), ch60 = 1, ch61..63 = 0
__device__ float g_u [BB * CP * NN];   // u = M' pe'   (scaled logits factor)
__device__ float g_Z [BB * CP * NN];   // Z = pe' P^T
__device__ float g_S [BB * NN * NN];   // logits / softmax probs (134 MB)
__device__ float g_M [CP * CP];        // sqrt(384) * [Wq|bq]^T [Wk|bk], zero-padded
__device__ float g_Wv[DD * CP];        // [Wv | bv | 0 0 0]

// ---------------------------------------------------------------------------
// 1. positional encoding: pos (B,3,N) -> pe' (B,64,N)
// ---------------------------------------------------------------------------
__global__ void pe_kernel(const float* __restrict__ pos) {
    int idx = blockIdx.x * blockDim.x + threadIdx.x;
    if (idx >= BB * NN) return;
    int b = idx / NN, n = idx % NN;
    const float* p = pos + b * 3 * NN;
    float* pe = g_pe + b * CP * NN;
#pragma unroll
    for (int c = 0; c < 3; c++) {
        float v = p[c * NN + n];
        float f = 1.0f;
#pragma unroll
        for (int k = 0; k < NF; k++) {
            float s, co;
            sincosf(v * f, &s, &co);
            pe[(c * 2 * NF + k) * NN + n]      = s;
            pe[(c * 2 * NF + NF + k) * NN + n] = co;
            f *= 2.0f;
        }
    }
    pe[60 * NN + n] = 1.0f;
    pe[61 * NN + n] = 0.0f;
    pe[62 * NN + n] = 0.0f;
    pe[63 * NN + n] = 0.0f;
}

// ---------------------------------------------------------------------------
// 2. precompute M' = sqrt(DD) * [Wq|bq]^T [Wk|bk]  (64x64, zero padded)
//    and Wv' = [Wv | bv | 0]
// ---------------------------------------------------------------------------
__global__ void prep_kernel(const float* __restrict__ Wq, const float* __restrict__ bq,
                            const float* __restrict__ Wk, const float* __restrict__ bk,
                            const float* __restrict__ Wv, const float* __restrict__ bv) {
    int idx = blockIdx.x * blockDim.x + threadIdx.x;
    const float scale = sqrtf((float)DD);
    if (idx < CP * CP) {
        int i = idx / CP, j = idx % CP;
        float acc = 0.0f;
        if (i <= 60 && j <= 60) {
            for (int d = 0; d < DD; d++) {
                float aq = (i < 60) ? Wq[d * 60 + i] : bq[d];
                float ak = (j < 60) ? Wk[d * 60 + j] : bk[d];
                acc = fmaf(aq, ak, acc);
            }
            acc *= scale;
        }
        g_M[idx] = acc;
    } else {
        int r = idx - CP * CP;
        if (r < DD * CP) {
            int d = r / CP, c = r % CP;
            g_Wv[r] = (c < 60) ? Wv[d * 60 + c] : ((c == 60) ? bv[d] : 0.0f);
        }
    }
}

// ---------------------------------------------------------------------------
// 3/7. generic small GEMM: Out[b, i0+i, n0+n] = sum_{c<64} A[i][c] * Bm[b][c][n]
//      mode 0: A=g_M   (64x64),  Bm=g_pe, Out=g_u     (grid.y = 1)
//      mode 1: A=g_Wv  (384x64), Bm=g_Z,  Out=d_out   (grid.y = 6)
// ---------------------------------------------------------------------------
__global__ void __launch_bounds__(256) gemm64_kernel(int mode, float* __restrict__ OutParam) {
    __shared__ float As[64][64];
    __shared__ float Bs[64][128];
    const float* A  = mode ? g_Wv : g_M;
    const float* Bm = mode ? g_Z  : g_pe;
    float* Out      = mode ? OutParam : g_u;
    const int I     = mode ? DD : CP;

    int b  = blockIdx.z;
    int i0 = blockIdx.y * 64;
    int n0 = blockIdx.x * 128;
    int t  = threadIdx.x;

    const float* Ap = A + i0 * CP;
#pragma unroll
    for (int j = 0; j < 4; j++) {
        int idx = t + j * 256;          // 1024 float4 = 64*64/4
        int row = idx >> 4, c4 = idx & 15;
        *reinterpret_cast<float4*>(&As[row][c4 * 4]) =
            *reinterpret_cast<const float4*>(Ap + row * CP + c4 * 4);
    }
    const float* Bp = Bm + b * CP * NN + n0;
#pragma unroll
    for (int j = 0; j < 8; j++) {
        int idx = t + j * 256;          // 2048 float4 = 64*128/4
        int row = idx >> 5, c4 = idx & 31;
        *reinterpret_cast<float4*>(&Bs[row][c4 * 4]) =
            *reinterpret_cast<const float4*>(Bp + row * NN + c4 * 4);
    }
    __syncthreads();

    int tx = t & 15, ty = t >> 4;       // tx -> 8 n cols, ty -> 4 i rows
    float acc[4][8];
#pragma unroll
    for (int j = 0; j < 4; j++)
#pragma unroll
        for (int k = 0; k < 8; k++) acc[j][k] = 0.0f;

#pragma unroll 8
    for (int c = 0; c < 64; c++) {
        float a[4];
#pragma unroll
        for (int j = 0; j < 4; j++) a[j] = As[ty * 4 + j][c];
        float4 b0 = *reinterpret_cast<float4*>(&Bs[c][tx * 8]);
        float4 b1 = *reinterpret_cast<float4*>(&Bs[c][tx * 8 + 4]);
        float bb[8] = {b0.x, b0.y, b0.z, b0.w, b1.x, b1.y, b1.z, b1.w};
#pragma unroll
        for (int j = 0; j < 4; j++)
#pragma unroll
            for (int k = 0; k < 8; k++) acc[j][k] = fmaf(a[j], bb[k], acc[j][k]);
    }

    float* Op = Out + (size_t)b * I * NN + n0;
#pragma unroll
    for (int j = 0; j < 4; j++) {
        int i = i0 + ty * 4 + j;
        *reinterpret_cast<float4*>(Op + (size_t)i * NN + tx * 8) =
            make_float4(acc[j][0], acc[j][1], acc[j][2], acc[j][3]);
        *reinterpret_cast<float4*>(Op + (size_t)i * NN + tx * 8 + 4) =
            make_float4(acc[j][4], acc[j][5], acc[j][6], acc[j][7]);
    }
}

// ---------------------------------------------------------------------------
// 4. logits: S[b][n][m] = sum_{c<64} pe'[b][c][n] * u[b][c][m]
//    128x128 tile, K=64 in two 32-chunks, 8x8 microtile
// ---------------------------------------------------------------------------
__global__ void __launch_bounds__(256) s_kernel() {
    __shared__ float As[32][128];
    __shared__ float Bs[32][128];
    int b  = blockIdx.z;
    int n0 = blockIdx.y * 128;
    int m0 = blockIdx.x * 128;
    int t  = threadIdx.x;
    int tx = t & 15, ty = t >> 4;   // ty -> 8 n rows, tx -> 8 m cols

    const float* Ap = g_pe + b * CP * NN + n0;
    const float* Bp = g_u  + b * CP * NN + m0;

    float acc[8][8];
#pragma unroll
    for (int i = 0; i < 8; i++)
#pragma unroll
        for (int j = 0; j < 8; j++) acc[i][j] = 0.0f;

    for (int kk = 0; kk < 64; kk += 32) {
#pragma unroll
        for (int j = 0; j < 4; j++) {
            int idx = t + j * 256;       // 1024 float4 = 32*128/4
            int row = idx >> 5, c4 = idx & 31;
            *reinterpret_cast<float4*>(&As[row][c4 * 4]) =
                *reinterpret_cast<const float4*>(Ap + (kk + row) * NN + c4 * 4);
            *reinterpret_cast<float4*>(&Bs[row][c4 * 4]) =
                *reinterpret_cast<const float4*>(Bp + (kk + row) * NN + c4 * 4);
        }
        __syncthreads();
#pragma unroll
        for (int kc = 0; kc < 32; kc++) {
            float4 a0 = *reinterpret_cast<float4*>(&As[kc][ty * 8]);
            float4 a1 = *reinterpret_cast<float4*>(&As[kc][ty * 8 + 4]);
            float4 b0 = *reinterpret_cast<float4*>(&Bs[kc][tx * 8]);
            float4 b1 = *reinterpret_cast<float4*>(&Bs[kc][tx * 8 + 4]);
            float a[8] = {a0.x, a0.y, a0.z, a0.w, a1.x, a1.y, a1.z, a1.w};
            float bb[8] = {b0.x, b0.y, b0.z, b0.w, b1.x, b1.y, b1.z, b1.w};
#pragma unroll
            for (int i = 0; i < 8; i++)
#pragma unroll
                for (int j = 0; j < 8; j++) acc[i][j] = fmaf(a[i], bb[j], acc[i][j]);
        }
        __syncthreads();
    }

    float* Sp = g_S + (size_t)b * NN * NN;
#pragma unroll
    for (int i = 0; i < 8; i++) {
        size_t off = (size_t)(n0 + ty * 8 + i) * NN + m0 + tx * 8;
        *reinterpret_cast<float4*>(Sp + off)     = make_float4(acc[i][0], acc[i][1], acc[i][2], acc[i][3]);
        *reinterpret_cast<float4*>(Sp + off + 4) = make_float4(acc[i][4], acc[i][5], acc[i][6], acc[i][7]);
    }
}

// ---------------------------------------------------------------------------
// 5. row softmax over m (in place in g_S)
// ---------------------------------------------------------------------------
__global__ void __launch_bounds__(256) softmax_kernel() {
    size_t row = blockIdx.x;             // b*NN + n
    float* S = g_S + row * NN;
    int t = threadIdx.x;
    __shared__ float red[256];

    float x[8];
    float mx = -1e30f;
#pragma unroll
    for (int i = 0; i < 8; i++) { x[i] = S[t + i * 256]; mx = fmaxf(mx, x[i]); }
    red[t] = mx; __syncthreads();
    for (int s = 128; s > 0; s >>= 1) {
        if (t < s) red[t] = fmaxf(red[t], red[t + s]);
        __syncthreads();
    }
    mx = red[0]; __syncthreads();

    float sum = 0.0f;
#pragma unroll
    for (int i = 0; i < 8; i++) { x[i] = expf(x[i] - mx); sum += x[i]; }
    red[t] = sum; __syncthreads();
    for (int s = 128; s > 0; s >>= 1) {
        if (t < s) red[t] += red[t + s];
        __syncthreads();
    }
    float inv = 1.0f / red[0];
#pragma unroll
    for (int i = 0; i < 8; i++) S[t + i * 256] = x[i] * inv;
}

// ---------------------------------------------------------------------------
// 6. Z[b][c][n] = sum_m P[b][n][m] * pe'[b][c][m]   (m split 4-ways, atomicAdd)
// ---------------------------------------------------------------------------
__global__ void zero_z_kernel() {
    int idx = blockIdx.x * blockDim.x + threadIdx.x;
    if (idx < BB * CP * NN) g_Z[idx] = 0.0f;
}

__global__ void __launch_bounds__(256) z_kernel() {
    __shared__ float Ps[128][33];
    __shared__ float pes[64][33];
    int b    = blockIdx.z;
    int n0   = blockIdx.x * 128;
    int mseg = blockIdx.y;               // 0..3, 512 m each
    int t  = threadIdx.x;
    int tx = t & 15, ty = t >> 4;        // tx -> 4 c rows, ty -> 8 n cols

    const float* pep = g_pe + b * CP * NN;
    const float* Pp  = g_S + (size_t)b * NN * NN;

    float acc[4][8];
#pragma unroll
    for (int j = 0; j < 4; j++)
#pragma unroll
        for (int k = 0; k < 8; k++) acc[j][k] = 0.0f;

    int mend = mseg * 512 + 512;
    for (int m0 = mseg * 512; m0 < mend; m0 += 32) {
#pragma unroll
        for (int j = 0; j < 8; j++) {    // pes 64x32
            int idx = t + j * 256;
            int row = idx >> 5, col = idx & 31;
            pes[row][col] = pep[row * NN + m0 + col];
        }
#pragma unroll
        for (int j = 0; j < 16; j++) {   // Ps 128x32
            int idx = t + j * 256;
            int row = idx >> 5, col = idx & 31;
            Ps[row][col] = Pp[(size_t)(n0 + row) * NN + m0 + col];
        }
        __syncthreads();
#pragma unroll 4
        for (int mm = 0; mm < 32; mm++) {
            float a[4], bb[8];
#pragma unroll
            for (int j = 0; j < 4; j++) a[j] = pes[tx * 4 + j][mm];
#pragma unroll
            for (int k = 0; k < 8; k++) bb[k] = Ps[ty * 8 + k][mm];
#pragma unroll
            for (int j = 0; j < 4; j++)
#pragma unroll
                for (int k = 0; k < 8; k++) acc[j][k] = fmaf(a[j], bb[k], acc[j][k]);
        }
        __syncthreads();
    }

    float* Zp = g_Z + b * CP * NN;
#pragma unroll
    for (int j = 0; j < 4; j++)
#pragma unroll
        for (int k = 0; k < 8; k++)
            atomicAdd(&Zp[(tx * 4 + j) * NN + n0 + ty * 8 + k], acc[j][k]);
}

// ---------------------------------------------------------------------------
extern "C" void kernel_launch(void* const* d_in, const int* in_sizes, int n_in,
                              void* d_out, int out_size) {
    const float* pos = (const float*)d_in[0];
    const float* Wq  = (const float*)d_in[1];
    const float* bq  = (const float*)d_in[2];
    const float* Wk  = (const float*)d_in[3];
    const float* bk  = (const float*)d_in[4];
    const float* Wv  = (const float*)d_in[5];
    const float* bv  = (const float*)d_in[6];
    float* out = (float*)d_out;

    pe_kernel<<<(BB * NN + 255) / 256, 256>>>(pos);
    prep_kernel<<<(CP * CP + DD * CP + 255) / 256, 256>>>(Wq, bq, Wk, bk, Wv, bv);
    zero_z_kernel<<<(BB * CP * NN + 255) / 256, 256>>>();

    // u = M' pe'
    gemm64_kernel<<<dim3(NN / 128, 1, BB), 256>>>(0, nullptr);
    // S = pe'^T u  (scaled logits)
    s_kernel<<<dim3(NN / 128, NN / 128, BB), 256>>>();
    // P = softmax(S)
    softmax_kernel<<<BB * NN, 256>>>();
    // Z = pe' P^T
    z_kernel<<<dim3(NN / 128, 4, BB), 256>>>();
    // out = Wv' Z
    gemm64_kernel<<<dim3(NN / 128, DD / 64, BB), 256>>>(1, out);
}

// round 3
// speedup vs baseline: 1.5586x; 1.5586x over previous
#include <cuda_runtime.h>
#include <math.h>
#include <stdint.h>

#define BB 8
#define NN 2048
#define DD 384
#define CP 64     // padded channel count (60 enc + 1 ones + 3 zero pad)
#define NF 10

// ---- scratch (device globals; no allocation allowed) ----
__device__ float g_pe[BB * CP * NN];   // pe' : (b, 64, N), ch60 = 1, ch61..63 = 0
__device__ float g_u [BB * CP * NN];   // u = M' pe'   (scaled logits factor)
__device__ float g_Z [BB * CP * NN];   // Z = pe' P^T / l
__device__ float g_M [CP * CP];        // sqrt(384) * [Wq|bq]^T [Wk|bk], zero-padded
__device__ float g_Wv[DD * CP];        // [Wv | bv | 0 0 0]

typedef unsigned long long ull;

__device__ __forceinline__ ull pk2(float lo, float hi) {
    ull d; asm("mov.b64 %0, {%1, %2};" : "=l"(d) : "f"(lo), "f"(hi)); return d;
}
__device__ __forceinline__ void upk2(ull v, float& lo, float& hi) {
    asm("mov.b64 {%0, %1}, %2;" : "=f"(lo), "=f"(hi) : "l"(v));
}
__device__ __forceinline__ ull fma2(ull a, ull b, ull c) {
    ull d; asm("fma.rn.f32x2 %0, %1, %2, %3;" : "=l"(d) : "l"(a), "l"(b), "l"(c)); return d;
}
__device__ __forceinline__ ull mul2(ull a, ull b) {
    ull d; asm("mul.rn.f32x2 %0, %1, %2;" : "=l"(d) : "l"(a), "l"(b)); return d;
}

// ---------------------------------------------------------------------------
// 1. positional encoding: pos (B,3,N) -> pe' (B,64,N)
// ---------------------------------------------------------------------------
__global__ void pe_kernel(const float* __restrict__ pos) {
    int idx = blockIdx.x * blockDim.x + threadIdx.x;
    if (idx >= BB * NN) return;
    int b = idx / NN, n = idx % NN;
    const float* p = pos + b * 3 * NN;
    float* pe = g_pe + b * CP * NN;
#pragma unroll
    for (int c = 0; c < 3; c++) {
        float v = p[c * NN + n];
        float f = 1.0f;
#pragma unroll
        for (int k = 0; k < NF; k++) {
            float s, co;
            sincosf(v * f, &s, &co);
            pe[(c * 2 * NF + k) * NN + n]      = s;
            pe[(c * 2 * NF + NF + k) * NN + n] = co;
            f *= 2.0f;
        }
    }
    pe[60 * NN + n] = 1.0f;
    pe[61 * NN + n] = 0.0f;
    pe[62 * NN + n] = 0.0f;
    pe[63 * NN + n] = 0.0f;
}

// ---------------------------------------------------------------------------
// 2. precompute M' = sqrt(DD) * [Wq|bq]^T [Wk|bk]  (64x64, zero padded)
//    and Wv' = [Wv | bv | 0]
// ---------------------------------------------------------------------------
__global__ void prep_kernel(const float* __restrict__ Wq, const float* __restrict__ bq,
                            const float* __restrict__ Wk, const float* __restrict__ bk,
                            const float* __restrict__ Wv, const float* __restrict__ bv) {
    int idx = blockIdx.x * blockDim.x + threadIdx.x;
    const float scale = sqrtf((float)DD);
    if (idx < CP * CP) {
        int i = idx / CP, j = idx % CP;
        float acc = 0.0f;
        if (i <= 60 && j <= 60) {
            for (int d = 0; d < DD; d++) {
                float aq = (i < 60) ? Wq[d * 60 + i] : bq[d];
                float ak = (j < 60) ? Wk[d * 60 + j] : bk[d];
                acc = fmaf(aq, ak, acc);
            }
            acc *= scale;
        }
        g_M[idx] = acc;
    } else {
        int r = idx - CP * CP;
        if (r < DD * CP) {
            int d = r / CP, c = r % CP;
            g_Wv[r] = (c < 60) ? Wv[d * 60 + c] : ((c == 60) ? bv[d] : 0.0f);
        }
    }
}

// ---------------------------------------------------------------------------
// 3/5. small GEMM: Out[b, i0+i, n0+n] = sum_{c<64} A[i][c] * Bm[b][c][n]
//      mode 0: A=g_M   (64x64),  Bm=g_pe, Out=g_u
//      mode 1: A=g_Wv  (384x64), Bm=g_Z,  Out=d_out
// ---------------------------------------------------------------------------
__global__ void __launch_bounds__(256) gemm64_kernel(int mode, float* __restrict__ OutParam) {
    __shared__ float As[64][64];
    __shared__ float Bs[64][128];
    const float* A  = mode ? g_Wv : g_M;
    const float* Bm = mode ? g_Z  : g_pe;
    float* Out      = mode ? OutParam : g_u;
    const int I     = mode ? DD : CP;

    int b  = blockIdx.z;
    int i0 = blockIdx.y * 64;
    int n0 = blockIdx.x * 128;
    int t  = threadIdx.x;

    const float* Ap = A + i0 * CP;
#pragma unroll
    for (int j = 0; j < 4; j++) {
        int idx = t + j * 256;
        int row = idx >> 4, c4 = idx & 15;
        *reinterpret_cast<float4*>(&As[row][c4 * 4]) =
            *reinterpret_cast<const float4*>(Ap + row * CP + c4 * 4);
    }
    const float* Bp = Bm + b * CP * NN + n0;
#pragma unroll
    for (int j = 0; j < 8; j++) {
        int idx = t + j * 256;
        int row = idx >> 5, c4 = idx & 31;
        *reinterpret_cast<float4*>(&Bs[row][c4 * 4]) =
            *reinterpret_cast<const float4*>(Bp + row * NN + c4 * 4);
    }
    __syncthreads();

    int tx = t & 15, ty = t >> 4;
    float acc[4][8];
#pragma unroll
    for (int j = 0; j < 4; j++)
#pragma unroll
        for (int k = 0; k < 8; k++) acc[j][k] = 0.0f;

#pragma unroll 8
    for (int c = 0; c < 64; c++) {
        float a[4];
#pragma unroll
        for (int j = 0; j < 4; j++) a[j] = As[ty * 4 + j][c];
        float4 b0 = *reinterpret_cast<float4*>(&Bs[c][tx * 8]);
        float4 b1 = *reinterpret_cast<float4*>(&Bs[c][tx * 8 + 4]);
        float bb[8] = {b0.x, b0.y, b0.z, b0.w, b1.x, b1.y, b1.z, b1.w};
#pragma unroll
        for (int j = 0; j < 4; j++)
#pragma unroll
            for (int k = 0; k < 8; k++) acc[j][k] = fmaf(a[j], bb[k], acc[j][k]);
    }

    float* Op = Out + (size_t)b * I * NN + n0;
#pragma unroll
    for (int j = 0; j < 4; j++) {
        int i = i0 + ty * 4 + j;
        *reinterpret_cast<float4*>(Op + (size_t)i * NN + tx * 8) =
            make_float4(acc[j][0], acc[j][1], acc[j][2], acc[j][3]);
        *reinterpret_cast<float4*>(Op + (size_t)i * NN + tx * 8 + 4) =
            make_float4(acc[j][4], acc[j][5], acc[j][6], acc[j][7]);
    }
}

// ---------------------------------------------------------------------------
// 4. fused flash attention over the 64-channel factorization:
//    S[n][m] = sum_c pe'[c][n] u[c][m]; P = softmax_m(S);  Z[c][n] = sum_m P pe'[c][m] / l
//    one block = 128 query rows; loop over 16 key tiles of 128.
// ---------------------------------------------------------------------------
#define UP  140                    // Us pitch (swizzled: col -> col + (col>>5)*4)
#define PEP 76                     // PE (transposed pe m-tile) pitch: [m][c]
#define PMP 140                    // Pm pitch (same swizzle as Us)
#define OFF_AS 0
#define OFF_US (64 * 128)
#define OFF_PE (OFF_US + 64 * UP)
#define OFF_PM (OFF_PE + 128 * PEP)
#define SMEMF  (OFF_PM + 128 * PMP)   // 44800 floats = 179200 B

__global__ void __launch_bounds__(256, 1) fused_attn() {
    extern __shared__ float sm[];
    float* As = sm + OFF_AS;   // [64][128]  pe' n-tile (k-major)
    float* Us = sm + OFF_US;   // [64][UP]   u m-tile, column-swizzled
    float* PE = sm + OFF_PE;   // [128][PEP] pe' m-tile transposed: [m][c]
    float* Pm = sm + OFF_PM;   // [128][PMP] P tile, column-swizzled

    int b  = blockIdx.y;
    int n0 = blockIdx.x * 128;
    int t  = threadIdx.x;
    int tx = t & 15, ty = t >> 4, ty8 = ty * 8;
    int mph = tx * 8 + (tx >> 2) * 4;        // swizzled column base for m = 8*tx

    const float* peB = g_pe + b * CP * NN;
    const float* uB  = g_u  + b * CP * NN;

    // load A tile (pe' columns n0..n0+127), layout [c][n] direct
#pragma unroll
    for (int j = 0; j < 8; j++) {
        int idx = t + j * 256, row = idx >> 5, c4 = (idx & 31) * 4;
        *reinterpret_cast<float4*>(As + row * 128 + c4) =
            *reinterpret_cast<const float4*>(peB + row * NN + n0 + c4);
    }

    ull sacc[8][4];          // S microtile: 8 rows x 4 m-pairs
    ull zacc[8][2];          // Z acc: 8 rows x 2 c-pairs (c = 4*tx + 2*cp + h)
    float mrun[8], lrun[8];
#pragma unroll
    for (int i = 0; i < 8; i++) {
        mrun[i] = -1e30f; lrun[i] = 0.0f; zacc[i][0] = 0ULL; zacc[i][1] = 0ULL;
    }

    for (int mt = 0; mt < 16; mt++) {
        int m0 = mt * 128;
        // fill Us (u tile, swizzled columns)
#pragma unroll
        for (int j = 0; j < 8; j++) {
            int idx = t + j * 256, row = idx >> 5, c4 = idx & 31;
            float4 v = *reinterpret_cast<const float4*>(uB + row * NN + m0 + c4 * 4);
            *reinterpret_cast<float4*>(Us + row * UP + c4 * 4 + (c4 >> 3) * 4) = v;
        }
        // fill PE transposed: PE[m][c] = pe'[c][m0+m]
#pragma unroll
        for (int j = 0; j < 32; j++) {
            int idx = t + j * 256, c = idx >> 7, m = idx & 127;
            PE[m * PEP + c] = peB[c * NN + m0 + m];
        }
        __syncthreads();

        // ---- GEMM1: S = A^T U (K=64), f32x2 over m-pairs ----
#pragma unroll
        for (int i = 0; i < 8; i++) {
            sacc[i][0] = 0ULL; sacc[i][1] = 0ULL; sacc[i][2] = 0ULL; sacc[i][3] = 0ULL;
        }
#pragma unroll 4
        for (int k = 0; k < 64; k++) {
            float4 a0 = *reinterpret_cast<const float4*>(As + k * 128 + ty8);
            float4 a1 = *reinterpret_cast<const float4*>(As + k * 128 + ty8 + 4);
            ulonglong2 b01 = *reinterpret_cast<const ulonglong2*>(Us + k * UP + mph);
            ulonglong2 b23 = *reinterpret_cast<const ulonglong2*>(Us + k * UP + mph + 4);
            ull ad[8];
            ad[0] = pk2(a0.x, a0.x); ad[1] = pk2(a0.y, a0.y);
            ad[2] = pk2(a0.z, a0.z); ad[3] = pk2(a0.w, a0.w);
            ad[4] = pk2(a1.x, a1.x); ad[5] = pk2(a1.y, a1.y);
            ad[6] = pk2(a1.z, a1.z); ad[7] = pk2(a1.w, a1.w);
#pragma unroll
            for (int i = 0; i < 8; i++) {
                sacc[i][0] = fma2(ad[i], b01.x, sacc[i][0]);
                sacc[i][1] = fma2(ad[i], b01.y, sacc[i][1]);
                sacc[i][2] = fma2(ad[i], b23.x, sacc[i][2]);
                sacc[i][3] = fma2(ad[i], b23.y, sacc[i][3]);
            }
        }

        // ---- online softmax + write P tile ----
#pragma unroll
        for (int i = 0; i < 8; i++) {
            float s[8];
            upk2(sacc[i][0], s[0], s[1]); upk2(sacc[i][1], s[2], s[3]);
            upk2(sacc[i][2], s[4], s[5]); upk2(sacc[i][3], s[6], s[7]);
            float tm = fmaxf(fmaxf(fmaxf(s[0], s[1]), fmaxf(s[2], s[3])),
                             fmaxf(fmaxf(s[4], s[5]), fmaxf(s[6], s[7])));
            tm = fmaxf(tm, __shfl_xor_sync(0xffffffffu, tm, 8, 16));
            tm = fmaxf(tm, __shfl_xor_sync(0xffffffffu, tm, 4, 16));
            tm = fmaxf(tm, __shfl_xor_sync(0xffffffffu, tm, 2, 16));
            tm = fmaxf(tm, __shfl_xor_sync(0xffffffffu, tm, 1, 16));
            float nm = fmaxf(mrun[i], tm);
            float al = __expf(mrun[i] - nm);
            mrun[i] = nm;
            float p[8], rs = 0.0f;
#pragma unroll
            for (int j = 0; j < 8; j++) { p[j] = __expf(s[j] - nm); rs += p[j]; }
            lrun[i] = fmaf(lrun[i], al, rs);
            ull a2 = pk2(al, al);
            zacc[i][0] = mul2(zacc[i][0], a2);
            zacc[i][1] = mul2(zacc[i][1], a2);
            *reinterpret_cast<float4*>(Pm + (ty8 + i) * PMP + mph) =
                make_float4(p[0], p[1], p[2], p[3]);
            *reinterpret_cast<float4*>(Pm + (ty8 + i) * PMP + mph + 4) =
                make_float4(p[4], p[5], p[6], p[7]);
        }
        __syncthreads();

        // ---- GEMM2: Z[n][c] += sum_m P[n][m] pe'[c][m], f32x2 over c-pairs ----
#pragma unroll 2
        for (int mc = 0; mc < 128; mc += 4) {
            int mcp = mc + (mc >> 5) * 4;    // swizzled Pm column
            ulonglong2 q0 = *reinterpret_cast<const ulonglong2*>(PE + (mc + 0) * PEP + tx * 4);
            ulonglong2 q1 = *reinterpret_cast<const ulonglong2*>(PE + (mc + 1) * PEP + tx * 4);
            ulonglong2 q2 = *reinterpret_cast<const ulonglong2*>(PE + (mc + 2) * PEP + tx * 4);
            ulonglong2 q3 = *reinterpret_cast<const ulonglong2*>(PE + (mc + 3) * PEP + tx * 4);
#pragma unroll
            for (int i = 0; i < 8; i++) {
                float4 pv = *reinterpret_cast<const float4*>(Pm + (ty8 + i) * PMP + mcp);
                ull d0 = pk2(pv.x, pv.x), d1 = pk2(pv.y, pv.y);
                ull d2 = pk2(pv.z, pv.z), d3 = pk2(pv.w, pv.w);
                zacc[i][0] = fma2(d0, q0.x, zacc[i][0]);
                zacc[i][1] = fma2(d0, q0.y, zacc[i][1]);
                zacc[i][0] = fma2(d1, q1.x, zacc[i][0]);
                zacc[i][1] = fma2(d1, q1.y, zacc[i][1]);
                zacc[i][0] = fma2(d2, q2.x, zacc[i][0]);
                zacc[i][1] = fma2(d2, q2.y, zacc[i][1]);
                zacc[i][0] = fma2(d3, q3.x, zacc[i][0]);
                zacc[i][1] = fma2(d3, q3.y, zacc[i][1]);
            }
        }
        __syncthreads();
    }

    // ---- epilogue: reduce l across the 16 tx threads of each row, then
    //      normalize and write Z (layout (b, c, n)) ----
#pragma unroll
    for (int i = 0; i < 8; i++) {
        float l = lrun[i];
        l += __shfl_xor_sync(0xffffffffu, l, 8, 16);
        l += __shfl_xor_sync(0xffffffffu, l, 4, 16);
        l += __shfl_xor_sync(0xffffffffu, l, 2, 16);
        l += __shfl_xor_sync(0xffffffffu, l, 1, 16);
        lrun[i] = l;
    }
    float* Zb = g_Z + b * CP * NN;
#pragma unroll
    for (int i = 0; i < 8; i++) {
        float inv = 1.0f / lrun[i];
        float z0, z1, z2, z3;
        upk2(zacc[i][0], z0, z1);
        upk2(zacc[i][1], z2, z3);
        int n = n0 + ty8 + i;
        Zb[(tx * 4 + 0) * NN + n] = z0 * inv;
        Zb[(tx * 4 + 1) * NN + n] = z1 * inv;
        Zb[(tx * 4 + 2) * NN + n] = z2 * inv;
        Zb[(tx * 4 + 3) * NN + n] = z3 * inv;
    }
}

// ---------------------------------------------------------------------------
extern "C" void kernel_launch(void* const* d_in, const int* in_sizes, int n_in,
                              void* d_out, int out_size) {
    const float* pos = (const float*)d_in[0];
    const float* Wq  = (const float*)d_in[1];
    const float* bq  = (const float*)d_in[2];
    const float* Wk  = (const float*)d_in[3];
    const float* bk  = (const float*)d_in[4];
    const float* Wv  = (const float*)d_in[5];
    const float* bv  = (const float*)d_in[6];
    float* out = (float*)d_out;

    pe_kernel<<<(BB * NN + 255) / 256, 256>>>(pos);
    prep_kernel<<<(CP * CP + DD * CP + 255) / 256, 256>>>(Wq, bq, Wk, bk, Wv, bv);

    // u = M' pe'
    gemm64_kernel<<<dim3(NN / 128, 1, BB), 256>>>(0, nullptr);

    // fused S -> softmax -> Z
    cudaFuncSetAttribute(fused_attn, cudaFuncAttributeMaxDynamicSharedMemorySize,
                         SMEMF * (int)sizeof(float));
    fused_attn<<<dim3(NN / 128, BB), 256, SMEMF * sizeof(float)>>>();

    // out = Wv' Z
    gemm64_kernel<<<dim3(NN / 128, DD / 64, BB), 256>>>(1, out);
}

// round 4
// speedup vs baseline: 1.6820x; 1.0791x over previous
#include <cuda_runtime.h>
#include <math.h>
#include <stdint.h>

#define BB 8
#define NN 2048
#define DD 384
#define CP 64     // padded channel count (60 enc + 1 ones + 3 zero pad)
#define NF 10

// ---- scratch (device globals; no allocation allowed) ----
__device__ float g_pe[BB * CP * NN];   // pe' : (b, 64, N), ch60 = 1, ch61..63 = 0
__device__ float g_u [BB * CP * NN];   // u = M' pe'
__device__ float g_Z [BB * CP * NN];   // Z = pe' P^T / l
__device__ float g_M [CP * CP];        // sqrt(384)*[Wq|bq]^T[Wk|bk]; padding stays 0 (zero-init, never written)
__device__ float g_Wv[DD * CP];        // [Wv | bv | 0 0 0]

typedef unsigned long long ull;

__device__ __forceinline__ ull pk2(float lo, float hi) {
    ull d; asm("mov.b64 %0, {%1, %2};" : "=l"(d) : "f"(lo), "f"(hi)); return d;
}
__device__ __forceinline__ void upk2(ull v, float& lo, float& hi) {
    asm("mov.b64 {%0, %1}, %2;" : "=f"(lo), "=f"(hi) : "l"(v));
}
__device__ __forceinline__ ull fma2(ull a, ull b, ull c) {
    ull d; asm("fma.rn.f32x2 %0, %1, %2, %3;" : "=l"(d) : "l"(a), "l"(b), "l"(c)); return d;
}
__device__ __forceinline__ ull mul2(ull a, ull b) {
    ull d; asm("mul.rn.f32x2 %0, %1, %2;" : "=l"(d) : "l"(a), "l"(b)); return d;
}

// ---------------------------------------------------------------------------
// 1. positional encoding: pos (B,3,N) -> pe' (B,64,N)
// ---------------------------------------------------------------------------
__global__ void pe_kernel(const float* __restrict__ pos) {
    int idx = blockIdx.x * blockDim.x + threadIdx.x;
    if (idx >= BB * NN) return;
    int b = idx / NN, n = idx % NN;
    const float* p = pos + b * 3 * NN;
    float* pe = g_pe + b * CP * NN;
#pragma unroll
    for (int c = 0; c < 3; c++) {
        float v = p[c * NN + n];
        float f = 1.0f;
#pragma unroll
        for (int k = 0; k < NF; k++) {
            float s, co;
            sincosf(v * f, &s, &co);
            pe[(c * 2 * NF + k) * NN + n]      = s;
            pe[(c * 2 * NF + NF + k) * NN + n] = co;
            f *= 2.0f;
        }
    }
    pe[60 * NN + n] = 1.0f;
    pe[61 * NN + n] = 0.0f;
    pe[62 * NN + n] = 0.0f;
    pe[63 * NN + n] = 0.0f;
}

// ---------------------------------------------------------------------------
// 2. prep: warp-per-output for M' (61x61 dots of K=384), elementwise for Wv'
//    blocks [0, MBLK): M outputs;  blocks [MBLK, MBLK+WBLK): Wv copy
// ---------------------------------------------------------------------------
#define MOUT (61 * 61)
#define MBLK ((MOUT + 7) / 8)            // 8 warps per block
#define WBLK ((DD * CP + 255) / 256)

__global__ void __launch_bounds__(256) prep_kernel(
        const float* __restrict__ Wq, const float* __restrict__ bq,
        const float* __restrict__ Wk, const float* __restrict__ bk,
        const float* __restrict__ Wv, const float* __restrict__ bv) {
    int t = threadIdx.x;
    if (blockIdx.x < MBLK) {
        int w = blockIdx.x * 8 + (t >> 5);
        if (w >= MOUT) return;
        int i = w / 61, j = w % 61;
        int l = t & 31;
        float acc = 0.0f;
#pragma unroll
        for (int it = 0; it < 12; it++) {
            int d = l + it * 32;
            float aq = (i < 60) ? Wq[d * 60 + i] : bq[d];
            float ak = (j < 60) ? Wk[d * 60 + j] : bk[d];
            acc = fmaf(aq, ak, acc);
        }
#pragma unroll
        for (int s = 16; s > 0; s >>= 1)
            acc += __shfl_xor_sync(0xffffffffu, acc, s);
        if (l == 0) g_M[i * CP + j] = acc * sqrtf((float)DD);
    } else {
        int r = (blockIdx.x - MBLK) * 256 + t;
        if (r < DD * CP) {
            int d = r / CP, c = r % CP;
            g_Wv[r] = (c < 60) ? Wv[d * 60 + c] : ((c == 60) ? bv[d] : 0.0f);
        }
    }
}

// ---------------------------------------------------------------------------
// 3/5. small GEMM: Out[b, i0+i, n0+n] = sum_{c<64} A[i][c] * Bm[b][c][n]
// ---------------------------------------------------------------------------
__global__ void __launch_bounds__(256) gemm64_kernel(int mode, float* __restrict__ OutParam) {
    __shared__ float As[64][64];
    __shared__ float Bs[64][128];
    const float* A  = mode ? g_Wv : g_M;
    const float* Bm = mode ? g_Z  : g_pe;
    float* Out      = mode ? OutParam : g_u;
    const int I     = mode ? DD : CP;

    int b  = blockIdx.z;
    int i0 = blockIdx.y * 64;
    int n0 = blockIdx.x * 128;
    int t  = threadIdx.x;

    const float* Ap = A + i0 * CP;
#pragma unroll
    for (int j = 0; j < 4; j++) {
        int idx = t + j * 256;
        int row = idx >> 4, c4 = idx & 15;
        *reinterpret_cast<float4*>(&As[row][c4 * 4]) =
            *reinterpret_cast<const float4*>(Ap + row * CP + c4 * 4);
    }
    const float* Bp = Bm + b * CP * NN + n0;
#pragma unroll
    for (int j = 0; j < 8; j++) {
        int idx = t + j * 256;
        int row = idx >> 5, c4 = idx & 31;
        *reinterpret_cast<float4*>(&Bs[row][c4 * 4]) =
            *reinterpret_cast<const float4*>(Bp + row * NN + c4 * 4);
    }
    __syncthreads();

    int tx = t & 15, ty = t >> 4;
    float acc[4][8];
#pragma unroll
    for (int j = 0; j < 4; j++)
#pragma unroll
        for (int k = 0; k < 8; k++) acc[j][k] = 0.0f;

#pragma unroll 8
    for (int c = 0; c < 64; c++) {
        float a[4];
#pragma unroll
        for (int j = 0; j < 4; j++) a[j] = As[ty * 4 + j][c];
        float4 b0 = *reinterpret_cast<float4*>(&Bs[c][tx * 8]);
        float4 b1 = *reinterpret_cast<float4*>(&Bs[c][tx * 8 + 4]);
        float bb[8] = {b0.x, b0.y, b0.z, b0.w, b1.x, b1.y, b1.z, b1.w};
#pragma unroll
        for (int j = 0; j < 4; j++)
#pragma unroll
            for (int k = 0; k < 8; k++) acc[j][k] = fmaf(a[j], bb[k], acc[j][k]);
    }

    float* Op = Out + (size_t)b * I * NN + n0;
#pragma unroll
    for (int j = 0; j < 4; j++) {
        int i = i0 + ty * 4 + j;
        *reinterpret_cast<float4*>(Op + (size_t)i * NN + tx * 8) =
            make_float4(acc[j][0], acc[j][1], acc[j][2], acc[j][3]);
        *reinterpret_cast<float4*>(Op + (size_t)i * NN + tx * 8 + 4) =
            make_float4(acc[j][4], acc[j][5], acc[j][6], acc[j][7]);
    }
}

// ---------------------------------------------------------------------------
// 4. fused flash attention (512 threads, 4 rows/thread)
// ---------------------------------------------------------------------------
#define UP  140                    // Us pitch (swizzled: col -> col + (col>>5)*4)
#define PEP 76                     // PE (transposed pe m-tile) pitch: [m][c]
#define PMP 140                    // Pm pitch (same swizzle as Us)
#define OFF_AS 0
#define OFF_US (64 * 128)
#define OFF_PE (OFF_US + 64 * UP)
#define OFF_PM (OFF_PE + 128 * PEP)
#define SMEMF  (OFF_PM + 128 * PMP)   // 44800 floats = 179200 B

__global__ void __launch_bounds__(512, 1) fused_attn() {
    extern __shared__ float sm[];
    float* As = sm + OFF_AS;   // [64][128]  pe' n-tile (k-major)
    float* Us = sm + OFF_US;   // [64][UP]   u m-tile, column-swizzled
    float* PE = sm + OFF_PE;   // [128][PEP] pe' m-tile transposed: [m][c]
    float* Pm = sm + OFF_PM;   // [128][PMP] P tile, column-swizzled

    int b  = blockIdx.y;
    int n0 = blockIdx.x * 128;
    int t  = threadIdx.x;
    int tx = t & 15, tyy = t >> 4;           // tyy 0..31, 4 rows each
    int r0 = tyy * 4;
    int mph = tx * 8 + (tx >> 2) * 4;        // swizzled column base for m = 8*tx

    const float* peB = g_pe + b * CP * NN;
    const float* uB  = g_u  + b * CP * NN;

    // load A tile (pe' columns n0..n0+127), layout [c][n]
#pragma unroll
    for (int j = 0; j < 4; j++) {
        int idx = t + j * 512, row = idx >> 5, c4 = (idx & 31) * 4;
        *reinterpret_cast<float4*>(As + row * 128 + c4) =
            *reinterpret_cast<const float4*>(peB + row * NN + n0 + c4);
    }

    ull sacc[4][4];          // 4 rows x 4 m-pairs
    ull zacc[4][2];          // 4 rows x 2 c-pairs
    float mrun[4], lrun[4];
#pragma unroll
    for (int i = 0; i < 4; i++) {
        mrun[i] = -1e30f; lrun[i] = 0.0f; zacc[i][0] = 0ULL; zacc[i][1] = 0ULL;
    }

    for (int mt = 0; mt < 16; mt++) {
        int m0 = mt * 128;
        // fill Us (u tile, swizzled columns): 64x128
#pragma unroll
        for (int j = 0; j < 4; j++) {
            int idx = t + j * 512, row = idx >> 5, c4 = idx & 31;
            float4 v = *reinterpret_cast<const float4*>(uB + row * NN + m0 + c4 * 4);
            *reinterpret_cast<float4*>(Us + row * UP + c4 * 4 + (c4 >> 3) * 4) = v;
        }
        // fill PE transposed: PE[m][c] = pe'[c][m0+m]
#pragma unroll
        for (int j = 0; j < 16; j++) {
            int idx = t + j * 512, c = idx >> 7, m = idx & 127;
            PE[m * PEP + c] = peB[c * NN + m0 + m];
        }
        __syncthreads();

        // ---- GEMM1: S = A^T U (K=64) ----
#pragma unroll
        for (int i = 0; i < 4; i++) {
            sacc[i][0] = 0ULL; sacc[i][1] = 0ULL; sacc[i][2] = 0ULL; sacc[i][3] = 0ULL;
        }
#pragma unroll 4
        for (int k = 0; k < 64; k++) {
            float4 a0 = *reinterpret_cast<const float4*>(As + k * 128 + r0);
            ulonglong2 b01 = *reinterpret_cast<const ulonglong2*>(Us + k * UP + mph);
            ulonglong2 b23 = *reinterpret_cast<const ulonglong2*>(Us + k * UP + mph + 4);
            ull ad[4];
            ad[0] = pk2(a0.x, a0.x); ad[1] = pk2(a0.y, a0.y);
            ad[2] = pk2(a0.z, a0.z); ad[3] = pk2(a0.w, a0.w);
#pragma unroll
            for (int i = 0; i < 4; i++) {
                sacc[i][0] = fma2(ad[i], b01.x, sacc[i][0]);
                sacc[i][1] = fma2(ad[i], b01.y, sacc[i][1]);
                sacc[i][2] = fma2(ad[i], b23.x, sacc[i][2]);
                sacc[i][3] = fma2(ad[i], b23.y, sacc[i][3]);
            }
        }

        // ---- online softmax + write P tile ----
#pragma unroll
        for (int i = 0; i < 4; i++) {
            float s[8];
            upk2(sacc[i][0], s[0], s[1]); upk2(sacc[i][1], s[2], s[3]);
            upk2(sacc[i][2], s[4], s[5]); upk2(sacc[i][3], s[6], s[7]);
            float tm = fmaxf(fmaxf(fmaxf(s[0], s[1]), fmaxf(s[2], s[3])),
                             fmaxf(fmaxf(s[4], s[5]), fmaxf(s[6], s[7])));
            tm = fmaxf(tm, __shfl_xor_sync(0xffffffffu, tm, 8, 16));
            tm = fmaxf(tm, __shfl_xor_sync(0xffffffffu, tm, 4, 16));
            tm = fmaxf(tm, __shfl_xor_sync(0xffffffffu, tm, 2, 16));
            tm = fmaxf(tm, __shfl_xor_sync(0xffffffffu, tm, 1, 16));
            float nm = fmaxf(mrun[i], tm);
            float al = __expf(mrun[i] - nm);
            mrun[i] = nm;
            float p[8], rs = 0.0f;
#pragma unroll
            for (int j = 0; j < 8; j++) { p[j] = __expf(s[j] - nm); rs += p[j]; }
            lrun[i] = fmaf(lrun[i], al, rs);
            ull a2 = pk2(al, al);
            zacc[i][0] = mul2(zacc[i][0], a2);
            zacc[i][1] = mul2(zacc[i][1], a2);
            *reinterpret_cast<float4*>(Pm + (r0 + i) * PMP + mph) =
                make_float4(p[0], p[1], p[2], p[3]);
            *reinterpret_cast<float4*>(Pm + (r0 + i) * PMP + mph + 4) =
                make_float4(p[4], p[5], p[6], p[7]);
        }
        __syncthreads();

        // ---- GEMM2: Z[n][c] += sum_m P[n][m] pe'[c][m] ----
#pragma unroll 2
        for (int mc = 0; mc < 128; mc += 4) {
            int mcp = mc + (mc >> 5) * 4;    // swizzled Pm column
            ulonglong2 q0 = *reinterpret_cast<const ulonglong2*>(PE + (mc + 0) * PEP + tx * 4);
            ulonglong2 q1 = *reinterpret_cast<const ulonglong2*>(PE + (mc + 1) * PEP + tx * 4);
            ulonglong2 q2 = *reinterpret_cast<const ulonglong2*>(PE + (mc + 2) * PEP + tx * 4);
            ulonglong2 q3 = *reinterpret_cast<const ulonglong2*>(PE + (mc + 3) * PEP + tx * 4);
#pragma unroll
            for (int i = 0; i < 4; i++) {
                float4 pv = *reinterpret_cast<const float4*>(Pm + (r0 + i) * PMP + mcp);
                ull d0 = pk2(pv.x, pv.x), d1 = pk2(pv.y, pv.y);
                ull d2 = pk2(pv.z, pv.z), d3 = pk2(pv.w, pv.w);
                zacc[i][0] = fma2(d0, q0.x, zacc[i][0]);
                zacc[i][1] = fma2(d0, q0.y, zacc[i][1]);
                zacc[i][0] = fma2(d1, q1.x, zacc[i][0]);
                zacc[i][1] = fma2(d1, q1.y, zacc[i][1]);
                zacc[i][0] = fma2(d2, q2.x, zacc[i][0]);
                zacc[i][1] = fma2(d2, q2.y, zacc[i][1]);
                zacc[i][0] = fma2(d3, q3.x, zacc[i][0]);
                zacc[i][1] = fma2(d3, q3.y, zacc[i][1]);
            }
        }
        __syncthreads();
    }

    // ---- epilogue: reduce l across the 16 tx lanes, normalize, write Z ----
#pragma unroll
    for (int i = 0; i < 4; i++) {
        float l = lrun[i];
        l += __shfl_xor_sync(0xffffffffu, l, 8, 16);
        l += __shfl_xor_sync(0xffffffffu, l, 4, 16);
        l += __shfl_xor_sync(0xffffffffu, l, 2, 16);
        l += __shfl_xor_sync(0xffffffffu, l, 1, 16);
        lrun[i] = l;
    }
    float* Zb = g_Z + b * CP * NN;
#pragma unroll
    for (int i = 0; i < 4; i++) {
        float inv = 1.0f / lrun[i];
        float z0, z1, z2, z3;
        upk2(zacc[i][0], z0, z1);
        upk2(zacc[i][1], z2, z3);
        int n = n0 + r0 + i;
        Zb[(tx * 4 + 0) * NN + n] = z0 * inv;
        Zb[(tx * 4 + 1) * NN + n] = z1 * inv;
        Zb[(tx * 4 + 2) * NN + n] = z2 * inv;
        Zb[(tx * 4 + 3) * NN + n] = z3 * inv;
    }
}

// ---------------------------------------------------------------------------
extern "C" void kernel_launch(void* const* d_in, const int* in_sizes, int n_in,
                              void* d_out, int out_size) {
    const float* pos = (const float*)d_in[0];
    const float* Wq  = (const float*)d_in[1];
    const float* bq  = (const float*)d_in[2];
    const float* Wk  = (const float*)d_in[3];
    const float* bk  = (const float*)d_in[4];
    const float* Wv  = (const float*)d_in[5];
    const float* bv  = (const float*)d_in[6];
    float* out = (float*)d_out;

    pe_kernel<<<(BB * NN + 255) / 256, 256>>>(pos);
    prep_kernel<<<MBLK + WBLK, 256>>>(Wq, bq, Wk, bk, Wv, bv);

    // u = M' pe'
    gemm64_kernel<<<dim3(NN / 128, 1, BB), 256>>>(0, nullptr);

    // fused S -> softmax -> Z
    cudaFuncSetAttribute(fused_attn, cudaFuncAttributeMaxDynamicSharedMemorySize,
                         SMEMF * (int)sizeof(float));
    fused_attn<<<dim3(NN / 128, BB), 512, SMEMF * sizeof(float)>>>();

    // out = Wv' Z
    gemm64_kernel<<<dim3(NN / 128, DD / 64, BB), 256>>>(1, out);
}